// round 4
// baseline (speedup 1.0000x reference)
#include <cuda_runtime.h>
#include <cuda_bf16.h>

#define THREADS 256
#define ITER 4
#define ROWS_PER_BLOCK (THREADS * ITER)
#define GMAX 4096

__device__ float    g_acc[GMAX * 4];   // {count, sum11, sum24, pad} per graph; zero-init at load
__device__ unsigned g_sem;             // zero-init at load

__global__ void __launch_bounds__(THREADS)
fused_kernel(const float* __restrict__ nf,
             const int*   __restrict__ batch,
             const float* __restrict__ W1,   // [32,2]
             const float* __restrict__ b1,   // [32]
             const float* __restrict__ W2,   // [1,32]
             const float* __restrict__ b2,   // [1]
             float* __restrict__ out,
             int N, int G, int nblocks) {
    const int lane = threadIdx.x & 31;
    const int base = blockIdx.x * ROWS_PER_BLOCK;

    // ---- Phase 1: front-batched loads (deep MLP), 4 x 256 consecutive rows ----
    int   g[ITER];
    float v0[ITER], v1[ITER], c[ITER];
    #pragma unroll
    for (int it = 0; it < ITER; it++) {
        int i = base + it * THREADS + threadIdx.x;
        if (i < N) {
            g[it]  = __ldg(batch + i);
            const float* row = nf + (size_t)i * 128;
            v0[it] = __ldg(row + 11);   // MODIFIER_COL
            v1[it] = __ldg(row + 24);   // OWNER_COL
            c[it]  = 1.0f;
        } else {
            g[it] = -1; v0[it] = 0.0f; v1[it] = 0.0f; c[it] = 0.0f;
        }
    }

    // ---- Phase 2: warp-segmented reduce per iteration; only run leaders atomic ----
    #pragma unroll
    for (int it = 0; it < ITER; it++) {
        unsigned peers  = __match_any_sync(0xffffffffu, g[it]);
        int      leader = __ffs(peers) - 1;
        int      cnt    = __popc(peers);
        float a0 = v0[it], a1 = v1[it], ac = c[it];
        #pragma unroll
        for (int off = 16; off > 0; off >>= 1) {
            float t0 = __shfl_down_sync(0xffffffffu, a0, off);
            float t1 = __shfl_down_sync(0xffffffffu, a1, off);
            float tc = __shfl_down_sync(0xffffffffu, ac, off);
            if (lane + off < leader + cnt) { a0 += t0; a1 += t1; ac += tc; }
        }
        if (lane == leader && g[it] >= 0) {
            atomicAdd(&g_acc[g[it] * 4 + 0], ac);
            atomicAdd(&g_acc[g[it] * 4 + 1], a0);
            atomicAdd(&g_acc[g[it] * 4 + 2], a1);
        }
    }

    // ---- Phase 3: last block runs the MLP, writes out, resets scratch ----
    __threadfence();            // make this thread's atomics visible
    __syncthreads();            // all threads in block fenced
    __shared__ int s_last;
    if (threadIdx.x == 0) {
        unsigned t = atomicAdd(&g_sem, 1u);
        s_last = (t == (unsigned)(nblocks - 1));
    }
    __syncthreads();
    if (!s_last) return;
    __threadfence();            // acquire side: see all blocks' g_acc writes

    for (int gg = threadIdx.x; gg < G; gg += THREADS) {
        float cn = __ldcg(&g_acc[gg * 4 + 0]);
        float s0 = __ldcg(&g_acc[gg * 4 + 1]);
        float s1 = __ldcg(&g_acc[gg * 4 + 2]);
        float denom = fmaxf(cn, 1.0f);
        float a0 = 1.0f - s0 / denom;
        float a1 = 1.0f - s1 / denom;

        float acc = __ldg(b2);
        #pragma unroll
        for (int j = 0; j < 32; j++) {
            float h = fmaf(a0, __ldg(W1 + j * 2 + 0),
                      fmaf(a1, __ldg(W1 + j * 2 + 1), __ldg(b1 + j)));
            h = fmaxf(h, 0.0f);
            acc = fmaf(h, __ldg(W2 + j), acc);
        }
        float score = 1.0f / (1.0f + __expf(-acc));
        out[gg] = (cn > 0.0f) ? score : 0.0f;
    }

    __syncthreads();
    // Reset scratch for the next graph replay (first call sees static zeros).
    for (int k = threadIdx.x; k < G * 4; k += THREADS) g_acc[k] = 0.0f;
    if (threadIdx.x == 0) g_sem = 0u;
}

extern "C" void kernel_launch(void* const* d_in, const int* in_sizes, int n_in,
                              void* d_out, int out_size) {
    // metadata order: node_features, batch, graph_embedding(unused), W1, b1, W2, b2
    const float* nf    = (const float*)d_in[0];
    const int*   batch = (const int*)d_in[1];
    const float* W1    = (const float*)d_in[3];
    const float* b1    = (const float*)d_in[4];
    const float* W2    = (const float*)d_in[5];
    const float* b2    = (const float*)d_in[6];
    float*       out   = (float*)d_out;

    int N = in_sizes[1];   // number of nodes
    int G = out_size;      // number of graphs
    if (G > GMAX) G = GMAX;

    int nblocks = (N + ROWS_PER_BLOCK - 1) / ROWS_PER_BLOCK;
    fused_kernel<<<nblocks, THREADS>>>(nf, batch, W1, b1, W2, b2, out, N, G, nblocks);
}